// round 7
// baseline (speedup 1.0000x reference)
#include <cuda_runtime.h>
#include <cuda_bf16.h>
#include <cuda_fp16.h>
#include <stdint.h>

// ---------------- scratch (__device__ globals; no allocations) ----------------
__device__ float    g_L[4096 * 128];      // q | k | v | scale rows
__device__ float    g_c[1024 * 128];      // Z_d * exp(M_d - s[n][d])
__device__ float    g_qk[1024 * 1024];
__device__ unsigned g_Menc[1024];         // row max of qk, order-encoded uint
// V^T fp16 pairs, frag-order permuted: g_Bh[k*512 + u(P)], P = m/2 pair index
__device__ uint32_t g_Bh[128 * 512];

__device__ __forceinline__ float ex2(float x) {
    float y; asm("ex2.approx.ftz.f32 %0, %1;" : "=f"(y) : "f"(x)); return y;
}
__device__ __forceinline__ uint32_t smem_u32(const void* p) {
    uint32_t a;
    asm("{ .reg .u64 t; cvta.to.shared.u64 t, %1; cvt.u32.u64 %0, t; }" : "=r"(a) : "l"(p));
    return a;
}
__device__ __forceinline__ uint32_t pack_h2(float a, float b) {
    __half2 h = __floats2half2_rn(a, b);
    return *(uint32_t*)&h;
}
// order-preserving float<->uint (for atomicMax row-max)
__device__ __forceinline__ unsigned enc_f(float f) {
    unsigned u = __float_as_uint(f);
    return (u & 0x80000000u) ? ~u : (u | 0x80000000u);
}
__device__ __forceinline__ float dec_f(unsigned k) {
    return __uint_as_float((k & 0x80000000u) ? (k ^ 0x80000000u) : ~k);
}

// ---- JAX threefry2x32 (partitionable): key=(0,42), ctr=(0,i), out = o0^o1 ----
// All adds go through *one (==1, opaque kernel arg) -> IMAD on the fma pipe,
// leaving only SHF+LOP3 (+ISETP/SEL) on the alu pipe.
__device__ __forceinline__ unsigned int tf_bits(unsigned idx, unsigned one) {
    const unsigned K1 = 42u;
    const unsigned K2 = 42u ^ 0x1BD11BDAu;
    unsigned x0, x1;
    x1 = idx * one + K1;
    // round 1 folded (x0 was 0): x0 = x1
    x0 = x1;
    x1 = __funnelshift_l(x1, x1, 13) ^ x0;
#define R(r) { x0 = x0 * one + x1; x1 = __funnelshift_l(x1, x1, (r)) ^ x0; }
    R(15) R(26) R(6)
    x0 = x0 * one + K1;  x1 = x1 * one + (K2 + 1u);
    R(17) R(29) R(16) R(24)
    x0 = x0 * one + K2;  x1 = x1 * one + 2u;
    R(13) R(15) R(26) R(6)
    /* x0 += 0 */        x1 = x1 * one + (K1 + 3u);
    R(17) R(29) R(16) R(24)
    x0 = x0 * one + K1;  x1 = x1 * one + (K2 + 4u);
    R(13) R(15) R(26) R(6)
    x0 = x0 * one + K2;  x1 = x1 * one + 5u;
#undef R
    return x0 ^ x1;
}
// keep ⟺ (bits>>9) < 5033165 ⟺ bits < 5033165*512  (uniform<0.6 exact)
__device__ __forceinline__ float keep_or_zero(unsigned idx, float e, unsigned one) {
    return (tf_bits(idx, one) < 2576980480u) ? e : 0.f;
}

__device__ __forceinline__ void mma16816(float* d,
    uint32_t a0, uint32_t a1, uint32_t a2, uint32_t a3, uint32_t b0, uint32_t b1) {
    asm volatile("mma.sync.aligned.m16n8k16.row.col.f32.f16.f16.f32 "
        "{%0,%1,%2,%3}, {%4,%5,%6,%7}, {%8,%9}, {%0,%1,%2,%3};"
        : "+f"(d[0]), "+f"(d[1]), "+f"(d[2]), "+f"(d[3])
        : "r"(a0), "r"(a1), "r"(a2), "r"(a3), "r"(b0), "r"(b1));
}
#define LDSM_X4(r0, r1, r2, r3, addr) \
    asm volatile("ldmatrix.sync.aligned.m8n8.x4.shared.b16 {%0,%1,%2,%3}, [%4];" \
        : "=r"(r0), "=r"(r1), "=r"(r2), "=r"(r3) : "r"(addr))

#define CP_ASYNC16(dst, src) \
    asm volatile("cp.async.cg.shared.global [%0], [%1], 16;" :: "r"(dst), "l"(src) : "memory")
#define CP_COMMIT() asm volatile("cp.async.commit_group;" ::: "memory")
#define CP_WAIT0()  asm volatile("cp.async.wait_group 0;" ::: "memory")

// ---------------- 1) linear for 4 stacked inputs (direct W read) + M init ----
__global__ void lin_kernel(const float* __restrict__ x1, const float* __restrict__ x2,
                           const float* __restrict__ x3, const float* __restrict__ x4,
                           const float* __restrict__ W, const float* __restrict__ b) {
    __shared__ float xs[8][512];
    int t = threadIdx.x;                 // 128 threads
    int r0 = blockIdx.x * 8;
    if (blockIdx.x < 8) g_Menc[blockIdx.x * 128 + t] = 0u;   // -inf encoding
    const float* srcs[4] = {x1, x2, x3, x4};
#pragma unroll
    for (int i = 0; i < 8; ++i) {
        int fl4 = t + i * 128;
        int r = fl4 >> 7, cg = fl4 & 127;
        int gr = r0 + r;
        const float* src = srcs[gr >> 10];
        *(float4*)&xs[r][cg * 4] = *(const float4*)&src[(gr & 1023) * 512 + cg * 4];
    }
    __syncthreads();
    int j = t;
    float acc[8];
    float bj = b[j];
#pragma unroll
    for (int r = 0; r < 8; ++r) acc[r] = bj;
    const float4* Wr = (const float4*)(W + j * 512);
#pragma unroll 4
    for (int k4 = 0; k4 < 128; ++k4) {
        float4 wv = Wr[k4];
#pragma unroll
        for (int r = 0; r < 8; ++r) {
            acc[r] += xs[r][k4 * 4 + 0] * wv.x;
            acc[r] += xs[r][k4 * 4 + 1] * wv.y;
            acc[r] += xs[r][k4 * 4 + 2] * wv.z;
            acc[r] += xs[r][k4 * 4 + 3] * wv.w;
        }
    }
#pragma unroll
    for (int r = 0; r < 8; ++r) g_L[(r0 + r) * 128 + j] = acc[r];
}

// ---------------- 2) fused: column softmax (blocks 0-127) + vsplit (128-255) -
__global__ void csm_vsplit_kernel() {
    int t = threadIdx.x;                 // 256
    if (blockIdx.x < 128) {
        __shared__ float red[256];
        int d = blockIdx.x;
        const float* S = g_L + 3072 * 128;
        float mx = -1e30f;
        for (int n = t; n < 1024; n += 256) mx = fmaxf(mx, S[n * 128 + d]);
        red[t] = mx; __syncthreads();
        for (int s = 128; s >= 1; s >>= 1) { if (t < s) red[t] = fmaxf(red[t], red[t + s]); __syncthreads(); }
        float Md = red[0]; __syncthreads();
        float z = 0.f;
        for (int n = t; n < 1024; n += 256) z += __expf(S[n * 128 + d] - Md);
        red[t] = z; __syncthreads();
        for (int s = 128; s >= 1; s >>= 1) { if (t < s) red[t] += red[t + s]; __syncthreads(); }
        float Zd = red[0]; __syncthreads();
        for (int n = t; n < 1024; n += 256) g_c[n * 128 + d] = Zd * __expf(Md - S[n * 128 + d]);
    } else {
        __shared__ float tile[32][33];
        const float* V = g_L + 2048 * 128;
        int bid = blockIdx.x - 128;
        int mt = bid & 31, kt = bid >> 5;
#pragma unroll
        for (int i = 0; i < 4; ++i) {
            int fl = t + i * 256;
            int mi = fl >> 5, kj = fl & 31;
            tile[mi][kj] = V[(mt * 32 + mi) * 128 + kt * 32 + kj];
        }
        __syncthreads();
#pragma unroll
        for (int i = 0; i < 2; ++i) {
            int fl = t + i * 256;            // 0..511
            int ki = fl >> 4, mj = fl & 15;
            float v0 = tile[2 * mj][ki], v1 = tile[2 * mj + 1][ki];
            int k = kt * 32 + ki;
            int P = mt * 16 + mj;            // global pair index (m/2)
            int u = (P & ~31) + (P & 16) + ((P & 3) << 2) + ((P >> 2) & 3);
            g_Bh[k * 512 + u] = pack_h2(v0, v1);
        }
    }
}

// ---------------- 3) qk = q @ k^T, fused row-max via atomicMax ---------------
__global__ void qk_kernel() {
    __shared__ float qaT[64][64];
    __shared__ float kbT[64][64];
    const float* q = g_L;
    const float* kmat = g_L + 1024 * 128;
    int t = threadIdx.x;
    int bx = blockIdx.x, by = blockIdx.y;
    int tr = (t >> 4) << 2, tc = (t & 15) << 2;
    float acc[4][4] = {};
    for (int k0 = 0; k0 < 128; k0 += 64) {
        __syncthreads();
#pragma unroll
        for (int i = 0; i < 4; ++i) {
            int fl4 = t + i * 256;
            int r = fl4 >> 4, kg = fl4 & 15;
            float4 va = *(const float4*)&q[(by * 64 + r) * 128 + k0 + kg * 4];
            qaT[kg * 4 + 0][r] = va.x; qaT[kg * 4 + 1][r] = va.y;
            qaT[kg * 4 + 2][r] = va.z; qaT[kg * 4 + 3][r] = va.w;
            float4 vb = *(const float4*)&kmat[(bx * 64 + r) * 128 + k0 + kg * 4];
            kbT[kg * 4 + 0][r] = vb.x; kbT[kg * 4 + 1][r] = vb.y;
            kbT[kg * 4 + 2][r] = vb.z; kbT[kg * 4 + 3][r] = vb.w;
        }
        __syncthreads();
#pragma unroll 8
        for (int kx = 0; kx < 64; ++kx) {
            float a[4], bv[4];
            *(float4*)a  = *(const float4*)&qaT[kx][tr];
            *(float4*)bv = *(const float4*)&kbT[kx][tc];
#pragma unroll
            for (int i = 0; i < 4; ++i)
#pragma unroll
                for (int j = 0; j < 4; ++j) acc[i][j] += a[i] * bv[j];
        }
    }
#pragma unroll
    for (int i = 0; i < 4; ++i) {
        *(float4*)&g_qk[(by * 64 + tr + i) * 1024 + bx * 64 + tc] =
            make_float4(acc[i][0], acc[i][1], acc[i][2], acc[i][3]);
        float m = fmaxf(fmaxf(acc[i][0], acc[i][1]), fmaxf(acc[i][2], acc[i][3]));
        atomicMax(&g_Menc[by * 64 + tr + i], enc_f(m));
    }
}

// ---------------- 4) main: E->smem once, ldmatrix A-frags, 3 CTAs/SM ---------
// smem: qkrow(4096) | cvals(256) | Zsm(256) | V0(24576) | V1(24576) | E0(9216) | E1(9216)
#define SM_QK   0
#define SM_CV   4096
#define SM_Z    4352
#define SM_V0   4608
#define SM_V1   29184
#define SM_E0   53760
#define SM_E1   62976
#define SMEM_BYTES 72192
#define SROW 48     // V row stride in words (192B): conflict-free LDS.128
#define EROW 144    // E row stride in bytes (72 halfs): conflict-free STS/LDSM

__global__ void __launch_bounds__(256, 3)
main_kernel(float* __restrict__ out, unsigned one) {
    extern __shared__ char smem[];
    float* qkrow = (float*)(smem + SM_QK);
    float* cvals = (float*)(smem + SM_CV);
    float* Zsm   = (float*)(smem + SM_Z);
    uint32_t sb = smem_u32(smem);

    int t = threadIdx.x, w = t >> 5, lane = t & 31;
    int n = blockIdx.x;
    int d0c = blockIdx.y << 6;             // 0 or 64
    float Mn = dec_f(g_Menc[n]);
    const float4* gBh4 = (const float4*)g_Bh;

    // stage V chunk 0 into buf0
#pragma unroll
    for (int i = 0; i < 4; ++i) {
        int fl = t + i * 256;
        int row = fl >> 3, idx = fl & 7;
        CP_ASYNC16(sb + SM_V0 + (uint32_t)(row * SROW + idx * 4) * 4, gBh4 + row * 128 + idx);
    }
    CP_COMMIT();

    // qkrow (pre-subtract Mn), cvals (pre-mul log2e)
    {
        float4 v = *(const float4*)&g_qk[n * 1024 + t * 4];
        v.x -= Mn; v.y -= Mn; v.z -= Mn; v.w -= Mn;
        *(float4*)&qkrow[t * 4] = v;
        if (t < 64) cvals[t] = g_c[n * 128 + d0c + t] * 1.4426950408889634f;
    }
    CP_WAIT0();
    __syncthreads();

    // E-gen identity: thread owns one local d, one 16-m quarter per chunk
    int dl = t >> 2, mq = t & 3;
    float cL = cvals[dl];
    unsigned ibase = ((unsigned)n << 17) + ((unsigned)(d0c + dl) << 10);
    float zacc = 0.f;

    // GEMM identity: warp -> 16-d tile (w&3) x 64-col half (w>>2)
    int qa = lane & 3, qr = lane >> 2;
    int dt0 = (w & 3) << 4;
    int kh64 = (w >> 2) << 6;
    uint32_t lrow = (uint32_t)(dt0 + (lane & 15)) * EROW + ((lane >> 4) << 4); // +16B for col8
    float acc[8][4];
#pragma unroll
    for (int i = 0; i < 8; ++i)
#pragma unroll
        for (int j = 0; j < 4; ++j) acc[i][j] = 0.f;

#pragma unroll 1
    for (int c = 0; c < 16; ++c) {
        uint32_t ebase = sb + ((c & 1) ? SM_E1 : SM_E0);
        const uint32_t* VhS = (const uint32_t*)(smem + ((c & 1) ? SM_V1 : SM_V0));

        // ---- E-gen: 16 elements (fixed d, consecutive m) ----
        {
            int mb = c * 64 + mq * 16;
            const float* qp = &qkrow[mb];
            unsigned i0 = ibase + (unsigned)mb;
            uint32_t h[8];
#pragma unroll
            for (int j = 0; j < 4; ++j) {
                float4 q4 = *(const float4*)&qp[j * 4];
                float e0 = ex2(cL * q4.x), e1 = ex2(cL * q4.y);
                float e2 = ex2(cL * q4.z), e3 = ex2(cL * q4.w);
                zacc += (e0 + e1) + (e2 + e3);
                unsigned ij = i0 + (unsigned)(j * 4);
                float v0 = keep_or_zero(ij + 0u, e0, one);
                float v1 = keep_or_zero(ij + 1u, e1, one);
                float v2 = keep_or_zero(ij + 2u, e2, one);
                float v3 = keep_or_zero(ij + 3u, e3, one);
                h[2 * j]     = pack_h2(v0, v1);
                h[2 * j + 1] = pack_h2(v2, v3);
            }
            char* ep = smem + (ebase - sb) + dl * EROW + mq * 32;
            *(uint4*)ep       = make_uint4(h[0], h[1], h[2], h[3]);
            *(uint4*)(ep + 16) = make_uint4(h[4], h[5], h[6], h[7]);
        }

        CP_WAIT0();          // V(c) resident
        __syncthreads();     // E(c) visible; V(c+1) buffer free; E(c-1) readers done

        // prefetch V(c+1)
        if (c < 15) {
            uint32_t dstb = sb + ((c & 1) ? SM_V0 : SM_V1);
#pragma unroll
            for (int i = 0; i < 4; ++i) {
                int fl = t + i * 256;
                int row = fl >> 3, idx = fl & 7;
                CP_ASYNC16(dstb + (uint32_t)(row * SROW + idx * 4) * 4,
                           gBh4 + row * 128 + (c + 1) * 8 + idx);
            }
            CP_COMMIT();
        }

        // ---- GEMM on E(c), V(c) ----
#pragma unroll
        for (int mtp = 0; mtp < 2; ++mtp) {
            uint32_t a0[4], a1[4];
            LDSM_X4(a0[0], a0[1], a0[2], a0[3], ebase + lrow + (uint32_t)(mtp * 64));
            LDSM_X4(a1[0], a1[1], a1[2], a1[3], ebase + lrow + (uint32_t)(mtp * 64 + 32));
#pragma unroll
            for (int nt = 0; nt < 8; ++nt) {
                int boff = (kh64 + nt * 8 + qr) * SROW + mtp * 16 + qa * 4;
                uint4 bh = *(const uint4*)&VhS[boff];
                mma16816(acc[nt], a0[0], a0[1], a0[2], a0[3], bh.x, bh.y);
                mma16816(acc[nt], a1[0], a1[1], a1[2], a1[3], bh.z, bh.w);
            }
        }
    }

    // Z: quad-reduce (lanes sharing dl differ only in low 2 bits)
    zacc += __shfl_xor_sync(0xffffffffu, zacc, 1);
    zacc += __shfl_xor_sync(0xffffffffu, zacc, 2);
    if (mq == 0) Zsm[dl] = zacc;
    __syncthreads();

    float izA = 1.0f / (0.6f * Zsm[dt0 + qr]);
    float izB = 1.0f / (0.6f * Zsm[dt0 + qr + 8]);
    float* obA = out + ((long)n << 14) + (long)(d0c + dt0 + qr) * 128 + kh64 + qa * 2;
    float* obB = obA + 8 * 128;
#pragma unroll
    for (int nt = 0; nt < 8; ++nt) {
        *(float2*)&obA[nt * 8] = make_float2(acc[nt][0] * izA, acc[nt][1] * izA);
        *(float2*)&obB[nt * 8] = make_float2(acc[nt][2] * izB, acc[nt][3] * izB);
    }
}

// ---------------------------------------------------------------------------
extern "C" void kernel_launch(void* const* d_in, const int* in_sizes, int n_in,
                              void* d_out, int out_size) {
    const float* x1 = (const float*)d_in[0];
    const float* x2 = (const float*)d_in[1];
    const float* x3 = (const float*)d_in[2];
    const float* x4 = (const float*)d_in[3];
    const float* W  = (const float*)d_in[4];
    const float* b  = (const float*)d_in[5];
    float* out = (float*)d_out;

    cudaFuncSetAttribute(main_kernel, cudaFuncAttributeMaxDynamicSharedMemorySize, SMEM_BYTES);

    lin_kernel<<<512, 128>>>(x1, x2, x3, x4, W, b);       // launch 1
    csm_vsplit_kernel<<<256, 256>>>();                    // launch 2
    qk_kernel<<<dim3(16, 16), 256>>>();                   // launch 3
    main_kernel<<<dim3(1024, 2), 256, SMEM_BYTES>>>(out, 1u);  // launch 4 -> ncu
}